// round 4
// baseline (speedup 1.0000x reference)
#include <cuda_runtime.h>
#include <math.h>
#include <stdint.h>

// ---------------- problem constants ----------------
#define BB 2
#define SS 1024
#define TT 2048
#define HH 1024
#define NHD 8
#define NOPE 128
#define QHD 192
#define VD 128
#define QCOLS 1536
#define KVC 2048          // rope block of Wkv unused -> skip
#define EE 8
#define CAP 2048
#define INTER 1024
#define SHD 1024

// ---------------- device scratch ----------------
__device__ float g_hnorm[TT * HH];
__device__ float g_qfull[TT * QCOLS];
__device__ float g_kv[TT * KVC];
__device__ float g_attn[TT * HH];
__device__ float g_x1[TT * HH];
__device__ float g_h2[TT * HH];
__device__ float g_gu[TT * 2 * SHD];
__device__ float g_act[TT * SHD];
__device__ float g_mid[(size_t)EE * CAP * INTER];
__device__ int   g_cnt[EE];
__device__ int   g_tok[EE * CAP];
__device__ float g_coef[EE * CAP];

// ---------------- helpers ----------------
__device__ __forceinline__ uint32_t s2u(const void* p) {
    return (uint32_t)__cvta_generic_to_shared(p);
}
__device__ __forceinline__ unsigned f2tf(float f) {
    unsigned r; asm("cvt.rna.tf32.f32 %0, %1;" : "=r"(r) : "f"(f)); return r;
}
__device__ __forceinline__ void mma_tf32(float* c, const unsigned* a, const unsigned* b) {
    asm volatile("mma.sync.aligned.m16n8k8.row.col.f32.tf32.tf32.f32 "
                 "{%0,%1,%2,%3},{%4,%5,%6,%7},{%8,%9},{%0,%1,%2,%3};"
                 : "+f"(c[0]), "+f"(c[1]), "+f"(c[2]), "+f"(c[3])
                 : "r"(a[0]), "r"(a[1]), "r"(a[2]), "r"(a[3]), "r"(b[0]), "r"(b[1]));
}
__device__ __forceinline__ void cpa16(uint32_t d, const void* s) {
    asm volatile("cp.async.cg.shared.global [%0], [%1], 16;" :: "r"(d), "l"(s));
}
__device__ __forceinline__ void cpa_commit() { asm volatile("cp.async.commit_group;"); }
template <int N> __device__ __forceinline__ void cpa_wait() {
    asm volatile("cp.async.wait_group %0;" :: "n"(N));
}

// ---------------- RMSNorm ----------------
__global__ void rmsnorm_k(const float* __restrict__ x, const float* __restrict__ w,
                          float* __restrict__ y) {
    int row = blockIdx.x;
    const float* xr = x + (size_t)row * HH;
    float v[4];
    float s = 0.f;
#pragma unroll
    for (int l = 0; l < 4; l++) {
        v[l] = xr[threadIdx.x + l * 256];
        s += v[l] * v[l];
    }
    __shared__ float red[256];
    red[threadIdx.x] = s;
    __syncthreads();
    for (int off = 128; off > 0; off >>= 1) {
        if (threadIdx.x < off) red[threadIdx.x] += red[threadIdx.x + off];
        __syncthreads();
    }
    float scale = rsqrtf(red[0] * (1.0f / HH) + 1e-6f);
    float* yr = y + (size_t)row * HH;
#pragma unroll
    for (int l = 0; l < 4; l++) {
        int i = threadIdx.x + l * 256;
        yr[i] = v[l] * scale * w[i];
    }
}

// ---------------- tf32 GEMM, 3-stage cp.async pipeline ----------------
// C[M,N] = A[M,1024] @ W[N,1024]^T. Tile 128x128x16, 256 thr, warp 32x64.
// MODE 0 plain / 1 +residual / 2 expert-up silu->g_mid / 3 expert-down atomic
#define SMS 20
#define GTILE (128 * SMS)

template <int MODE>
__global__ void __launch_bounds__(256, 2) mma_gemm_k(
    const float* __restrict__ A, const float* __restrict__ W,
    float* __restrict__ C, int N, const float* __restrict__ R, size_t estride)
{
    extern __shared__ __align__(16) float dyn[];
    float* sA = dyn;                // [3][GTILE]
    float* sW = dyn + 3 * GTILE;    // [3][GTILE]
    __shared__ int   s_tok[128];
    __shared__ float s_cf[128];

    const int e  = blockIdx.z;
    const int m0 = blockIdx.y * 128;
    const int n0 = blockIdx.x * 128;
    const int tid = threadIdx.x;

    if (MODE == 2 || MODE == 3) {
        int n_e = g_cnt[e];
        if (m0 >= n_e) return;
        if (tid < 128) {
            int i = m0 + tid;
            bool ok = i < n_e;
            s_tok[tid] = ok ? g_tok[e * CAP + i] : -1;
            if (MODE == 3) s_cf[tid] = ok ? g_coef[e * CAP + i] : 0.f;
        }
        __syncthreads();
    }

    const float* Wbase = W + (size_t)e * estride + (size_t)n0 * 1024;
    const float* Arow  = (MODE == 3) ? (g_mid + ((size_t)e * CAP + m0) * 1024)
                                     : (A + (size_t)m0 * 1024);

    auto issue = [&](int stage, int it) {
        int k0 = it * 16;
        uint32_t da = s2u(sA + stage * GTILE);
        uint32_t dw = s2u(sW + stage * GTILE);
#pragma unroll
        for (int j = 0; j < 2; j++) {
            int q = tid + j * 256;
            int r = q >> 2, c4 = q & 3;
            const float* srcA;
            if (MODE == 2) {
                int tk = s_tok[r]; if (tk < 0) tk = 0;
                srcA = A + (size_t)tk * 1024 + k0 + c4 * 4;
            } else {
                srcA = Arow + (size_t)r * 1024 + k0 + c4 * 4;
            }
            uint32_t off = (uint32_t)(r * SMS + c4 * 4) * 4;
            cpa16(da + off, srcA);
            cpa16(dw + off, Wbase + (size_t)r * 1024 + k0 + c4 * 4);
        }
        cpa_commit();
    };

    const int wid = tid >> 5, lane = tid & 31;
    const int wm = wid & 3, wn = wid >> 2;
    const int lr = lane >> 2, lc = lane & 3;

    float acc[2][8][4] = {};

    issue(0, 0);
    issue(1, 1);
    for (int it = 0; it < 64; ++it) {
        int cur = it % 3;
        cpa_wait<1>();
        __syncthreads();
        if (it + 2 < 64) issue((it + 2) % 3, it + 2);
        const float* As = sA + cur * GTILE;
        const float* Ws = sW + cur * GTILE;
#pragma unroll
        for (int ks = 0; ks < 16; ks += 8) {
            unsigned af[2][4];
#pragma unroll
            for (int mt = 0; mt < 2; mt++) {
                int row = wm * 32 + mt * 16 + lr;
                int k = ks + lc;
                af[mt][0] = f2tf(As[row * SMS + k]);
                af[mt][1] = f2tf(As[(row + 8) * SMS + k]);
                af[mt][2] = f2tf(As[row * SMS + k + 4]);
                af[mt][3] = f2tf(As[(row + 8) * SMS + k + 4]);
            }
#pragma unroll
            for (int nt = 0; nt < 8; nt++) {
                unsigned bf[2];
                int n = wn * 64 + nt * 8 + lr;
                int k = ks + lc;
                bf[0] = f2tf(Ws[n * SMS + k]);
                bf[1] = f2tf(Ws[n * SMS + k + 4]);
                mma_tf32(acc[0][nt], af[0], bf);
                mma_tf32(acc[1][nt], af[1], bf);
            }
        }
    }

#pragma unroll
    for (int mt = 0; mt < 2; mt++)
#pragma unroll
    for (int i = 0; i < 2; i++) {
        int rloc = wm * 32 + mt * 16 + lr + i * 8;
#pragma unroll
        for (int nt = 0; nt < 8; nt++) {
            float v0 = acc[mt][nt][2 * i], v1 = acc[mt][nt][2 * i + 1];
            int col = n0 + wn * 64 + nt * 8 + 2 * lc;
            if (MODE == 0) {
                *(float2*)&C[(size_t)(m0 + rloc) * N + col] = make_float2(v0, v1);
            } else if (MODE == 1) {
                float2 rr = *(const float2*)&R[(size_t)(m0 + rloc) * N + col];
                *(float2*)&C[(size_t)(m0 + rloc) * N + col] = make_float2(v0 + rr.x, v1 + rr.y);
            } else if (MODE == 2) {
                if (s_tok[rloc] >= 0) {
                    float o0 = v0 / (1.f + __expf(-v0));
                    float o1 = v1 / (1.f + __expf(-v1));
                    *(float2*)&g_mid[((size_t)e * CAP + m0 + rloc) * 1024 + col] =
                        make_float2(o0, o1);
                }
            } else {
                int tk = s_tok[rloc];
                if (tk >= 0) {
                    float cf = s_cf[rloc];
                    atomicAdd(&C[(size_t)tk * 1024 + col],     cf * v0);
                    atomicAdd(&C[(size_t)tk * 1024 + col + 1], cf * v1);
                }
            }
        }
    }
}

// ---------------- tensor-core flash attention ----------------
// 64 q-rows per block, 4 warps (m16 each), K/V tiles of 64 double-buffered.
#define FQS 132   // Qs/Ks row stride (floats)
#define FVS 136   // Vs row stride
#define FPS 68    // Ps row stride
#define FL_SMEM ((64 * FQS + 2 * 64 * FQS + 2 * 64 * FVS + 64 * FPS) * 4)

__global__ void __launch_bounds__(128) flashmma_k(const float* __restrict__ qfull,
                                                  const float* __restrict__ kv,
                                                  float* __restrict__ out) {
    extern __shared__ __align__(16) float sm[];
    float* Qs = sm;                      // [64][FQS]
    float* Ks = Qs + 64 * FQS;           // [2][64][FQS]
    float* Vs = Ks + 2 * 64 * FQS;       // [2][64][FVS]
    float* Ps = Vs + 2 * 64 * FVS;       // [64][FPS]

    const int b = blockIdx.z, h = blockIdx.y, qt = blockIdx.x;
    const int tid = threadIdx.x, wid = tid >> 5, lane = tid & 31;
    const int lr = lane >> 2, lc = lane & 3;
    const int t0 = b * SS + qt * 64;
    const float scale = rsqrtf((float)QHD);

    // Q load (part of cp.async group 0)
    {
        uint32_t qb = s2u(Qs);
#pragma unroll
        for (int j = 0; j < 16; j++) {
            int q = tid + j * 128;
            int r = q >> 5, c4 = q & 31;
            cpa16(qb + (uint32_t)(r * FQS + c4 * 4) * 4,
                  qfull + (size_t)(t0 + r) * QCOLS + h * QHD + c4 * 4);
        }
    }
    auto issue_kv = [&](int stage, int kt) {
        int k0g = b * SS + kt * 64;
        uint32_t kb = s2u(Ks + stage * 64 * FQS);
        uint32_t vb = s2u(Vs + stage * 64 * FVS);
#pragma unroll
        for (int j = 0; j < 16; j++) {
            int q = tid + j * 128;
            int r = q >> 5, c4 = q & 31;
            const float* kvrow = kv + (size_t)(k0g + r) * KVC;
            cpa16(kb + (uint32_t)(r * FQS + c4 * 4) * 4, kvrow + h * NOPE + c4 * 4);
            cpa16(vb + (uint32_t)(r * FVS + c4 * 4) * 4, kvrow + NHD * NOPE + h * VD + c4 * 4);
        }
        cpa_commit();
    };
    issue_kv(0, 0);

    float m0r = -1e30f, m1r = -1e30f, l0 = 0.f, l1 = 0.f;
    float o[16][4];
#pragma unroll
    for (int nt = 0; nt < 16; nt++)
#pragma unroll
        for (int j = 0; j < 4; j++) o[nt][j] = 0.f;

    const int qrow = wid * 16 + lr;

    for (int kt = 0; kt <= qt; kt++) {
        int cur = kt & 1;
        cpa_wait<0>();
        __syncthreads();
        if (kt < qt) issue_kv(cur ^ 1, kt + 1);
        const float* Kb = Ks + cur * 64 * FQS;
        const float* Vb = Vs + cur * 64 * FVS;

        // S = Q K^T  (16 x 64 per warp)
        float sc[8][4] = {};
#pragma unroll
        for (int kk = 0; kk < 128; kk += 8) {
            unsigned a[4];
            a[0] = f2tf(Qs[qrow * FQS + kk + lc]);
            a[1] = f2tf(Qs[(qrow + 8) * FQS + kk + lc]);
            a[2] = f2tf(Qs[qrow * FQS + kk + lc + 4]);
            a[3] = f2tf(Qs[(qrow + 8) * FQS + kk + lc + 4]);
#pragma unroll
            for (int nt = 0; nt < 8; nt++) {
                unsigned bb[2];
                bb[0] = f2tf(Kb[(nt * 8 + lr) * FQS + kk + lc]);
                bb[1] = f2tf(Kb[(nt * 8 + lr) * FQS + kk + lc + 4]);
                mma_tf32(sc[nt], a, bb);
            }
        }
#pragma unroll
        for (int nt = 0; nt < 8; nt++)
#pragma unroll
            for (int j = 0; j < 4; j++) sc[nt][j] *= scale;
        if (kt == qt) {
#pragma unroll
            for (int nt = 0; nt < 8; nt++)
#pragma unroll
                for (int j = 0; j < 4; j++) {
                    int colg = kt * 64 + nt * 8 + 2 * lc + (j & 1);
                    int rowg = qt * 64 + qrow + (j >> 1) * 8;
                    if (colg > rowg) sc[nt][j] = -1e30f;
                }
        }
        // row softmax (rows qrow, qrow+8)
        float mx0 = -1e30f, mx1 = -1e30f;
#pragma unroll
        for (int nt = 0; nt < 8; nt++) {
            mx0 = fmaxf(mx0, fmaxf(sc[nt][0], sc[nt][1]));
            mx1 = fmaxf(mx1, fmaxf(sc[nt][2], sc[nt][3]));
        }
        mx0 = fmaxf(mx0, __shfl_xor_sync(0xffffffffu, mx0, 1));
        mx0 = fmaxf(mx0, __shfl_xor_sync(0xffffffffu, mx0, 2));
        mx1 = fmaxf(mx1, __shfl_xor_sync(0xffffffffu, mx1, 1));
        mx1 = fmaxf(mx1, __shfl_xor_sync(0xffffffffu, mx1, 2));
        float mn0 = fmaxf(m0r, mx0), mn1 = fmaxf(m1r, mx1);
        float a0 = __expf(m0r - mn0), a1 = __expf(m1r - mn1);
        float s0 = 0.f, s1 = 0.f;
#pragma unroll
        for (int nt = 0; nt < 8; nt++) {
            sc[nt][0] = __expf(sc[nt][0] - mn0);
            sc[nt][1] = __expf(sc[nt][1] - mn0);
            sc[nt][2] = __expf(sc[nt][2] - mn1);
            sc[nt][3] = __expf(sc[nt][3] - mn1);
            s0 += sc[nt][0] + sc[nt][1];
            s1 += sc[nt][2] + sc[nt][3];
        }
        s0 += __shfl_xor_sync(0xffffffffu, s0, 1);
        s0 += __shfl_xor_sync(0xffffffffu, s0, 2);
        s1 += __shfl_xor_sync(0xffffffffu, s1, 1);
        s1 += __shfl_xor_sync(0xffffffffu, s1, 2);
        l0 = l0 * a0 + s0; l1 = l1 * a1 + s1;
        m0r = mn0; m1r = mn1;
#pragma unroll
        for (int nt = 0; nt < 16; nt++) {
            o[nt][0] *= a0; o[nt][1] *= a0;
            o[nt][2] *= a1; o[nt][3] *= a1;
        }
        // P -> smem (same warp only)
#pragma unroll
        for (int nt = 0; nt < 8; nt++) {
            *(float2*)&Ps[qrow * FPS + nt * 8 + 2 * lc]       = make_float2(sc[nt][0], sc[nt][1]);
            *(float2*)&Ps[(qrow + 8) * FPS + nt * 8 + 2 * lc] = make_float2(sc[nt][2], sc[nt][3]);
        }
        __syncwarp();
        // O += P V   (k = 64 keys, n = 128 dims)
#pragma unroll
        for (int kk = 0; kk < 64; kk += 8) {
            unsigned a[4];
            a[0] = f2tf(Ps[qrow * FPS + kk + lc]);
            a[1] = f2tf(Ps[(qrow + 8) * FPS + kk + lc]);
            a[2] = f2tf(Ps[qrow * FPS + kk + lc + 4]);
            a[3] = f2tf(Ps[(qrow + 8) * FPS + kk + lc + 4]);
#pragma unroll
            for (int nt = 0; nt < 16; nt++) {
                unsigned bb[2];
                bb[0] = f2tf(Vb[(kk + lc) * FVS + nt * 8 + lr]);
                bb[1] = f2tf(Vb[(kk + lc + 4) * FVS + nt * 8 + lr]);
                mma_tf32(o[nt], a, bb);
            }
        }
        __syncwarp();
    }

    float inv0 = 1.f / l0, inv1 = 1.f / l1;
    int r0 = t0 + qrow, r1 = r0 + 8;
#pragma unroll
    for (int nt = 0; nt < 16; nt++) {
        int col = h * VD + nt * 8 + 2 * lc;
        *(float2*)&out[(size_t)r0 * HH + col] = make_float2(o[nt][0] * inv0, o[nt][1] * inv0);
        *(float2*)&out[(size_t)r1 * HH + col] = make_float2(o[nt][2] * inv1, o[nt][3] * inv1);
    }
}

// ---------------- router ----------------
__global__ void zero_cnt_k() {
    if (threadIdx.x < EE) g_cnt[threadIdx.x] = 0;
}

__global__ void gate_k(const float* __restrict__ h2, const float* __restrict__ gw) {
    int warp = (blockIdx.x * blockDim.x + threadIdx.x) >> 5;
    int lane = threadIdx.x & 31;
    if (warp >= TT) return;
    const float* hr = h2 + (size_t)warp * HH;
    float hv[32];
#pragma unroll
    for (int i = 0; i < 32; i++) hv[i] = hr[lane + i * 32];
    float logits[EE];
#pragma unroll
    for (int e = 0; e < EE; e++) {
        const float* wr = gw + e * HH;
        float s = 0.f;
#pragma unroll
        for (int i = 0; i < 32; i++) s = fmaf(hv[i], wr[lane + i * 32], s);
#pragma unroll
        for (int off = 16; off >= 1; off >>= 1)
            s += __shfl_xor_sync(0xffffffffu, s, off);
        logits[e] = s;
    }
    if (lane == 0) {
        int i0 = 0; float v0 = logits[0];
#pragma unroll
        for (int e = 1; e < EE; e++)
            if (logits[e] > v0) { v0 = logits[e]; i0 = e; }
        int i1 = -1; float v1 = -1e30f;
#pragma unroll
        for (int e = 0; e < EE; e++)
            if (e != i0 && logits[e] > v1) { v1 = logits[e]; i1 = e; }
        float r = __expf(v1 - v0);
        float z = 1.f + r;
        float w0 = 1.f / z, w1 = r / z;
        int p0 = atomicAdd(&g_cnt[i0], 1);
        g_tok[i0 * CAP + p0] = warp; g_coef[i0 * CAP + p0] = w0;
        int p1 = atomicAdd(&g_cnt[i1], 1);
        g_tok[i1 * CAP + p1] = warp; g_coef[i1 * CAP + p1] = w1;
    }
}

// ---------------- GLU ----------------
__global__ void glu_k() {
    int idx = blockIdx.x * blockDim.x + threadIdx.x;
    if (idx >= TT * SHD) return;
    int t = idx >> 10;
    int i = idx & 1023;
    float g = g_gu[(size_t)t * (2 * SHD) + i];
    float u = g_gu[(size_t)t * (2 * SHD) + SHD + i];
    g_act[idx] = g / (1.f + __expf(-g)) * u;
}

// ---------------- launch ----------------
extern "C" void kernel_launch(void* const* d_in, const int* in_sizes, int n_in,
                              void* d_out, int out_size) {
    const float* x   = (const float*)d_in[0];
    const float* ln1 = (const float*)d_in[2];
    const float* ln2 = (const float*)d_in[3];
    const float* Wq  = (const float*)d_in[4];
    const float* Wkv = (const float*)d_in[5];
    const float* Wo  = (const float*)d_in[6];
    const float* gw  = (const float*)d_in[7];
    const float* w1  = (const float*)d_in[8];
    const float* w2  = (const float*)d_in[9];
    const float* sgu = (const float*)d_in[10];
    const float* sdn = (const float*)d_in[11];
    float* out = (float*)d_out;

    void *p_hnorm, *p_qfull, *p_kv, *p_attn, *p_x1, *p_h2, *p_gu, *p_act;
    cudaGetSymbolAddress(&p_hnorm, g_hnorm);
    cudaGetSymbolAddress(&p_qfull, g_qfull);
    cudaGetSymbolAddress(&p_kv,    g_kv);
    cudaGetSymbolAddress(&p_attn,  g_attn);
    cudaGetSymbolAddress(&p_x1,    g_x1);
    cudaGetSymbolAddress(&p_h2,    g_h2);
    cudaGetSymbolAddress(&p_gu,    g_gu);
    cudaGetSymbolAddress(&p_act,   g_act);

    const int GEMM_SMEM = 3 * GTILE * 4 * 2;   // 61440 B
    static bool s_attr = false;
    if (!s_attr) {
        s_attr = true;
        cudaFuncSetAttribute(mma_gemm_k<0>, cudaFuncAttributeMaxDynamicSharedMemorySize, GEMM_SMEM);
        cudaFuncSetAttribute(mma_gemm_k<1>, cudaFuncAttributeMaxDynamicSharedMemorySize, GEMM_SMEM);
        cudaFuncSetAttribute(mma_gemm_k<2>, cudaFuncAttributeMaxDynamicSharedMemorySize, GEMM_SMEM);
        cudaFuncSetAttribute(mma_gemm_k<3>, cudaFuncAttributeMaxDynamicSharedMemorySize, GEMM_SMEM);
        cudaFuncSetAttribute(flashmma_k, cudaFuncAttributeMaxDynamicSharedMemorySize, FL_SMEM);
    }

    // attention block
    rmsnorm_k<<<TT, 256>>>(x, ln1, (float*)p_hnorm);
    mma_gemm_k<0><<<dim3(QCOLS / 128, TT / 128), 256, GEMM_SMEM>>>(
        (const float*)p_hnorm, Wq, (float*)p_qfull, QCOLS, nullptr, 0);
    mma_gemm_k<0><<<dim3(KVC / 128, TT / 128), 256, GEMM_SMEM>>>(
        (const float*)p_hnorm, Wkv, (float*)p_kv, KVC, nullptr, 0);
    flashmma_k<<<dim3(SS / 64, NHD, BB), 128, FL_SMEM>>>(
        (const float*)p_qfull, (const float*)p_kv, (float*)p_attn);
    mma_gemm_k<1><<<dim3(HH / 128, TT / 128), 256, GEMM_SMEM>>>(
        (const float*)p_attn, Wo, (float*)p_x1, HH, x, 0);

    // MoE block
    rmsnorm_k<<<TT, 256>>>((const float*)p_x1, ln2, (float*)p_h2);
    zero_cnt_k<<<1, 32>>>();
    gate_k<<<TT / 8, 256>>>((const float*)p_h2, gw);
    mma_gemm_k<0><<<dim3((2 * SHD) / 128, TT / 128), 256, GEMM_SMEM>>>(
        (const float*)p_h2, sgu, (float*)p_gu, 2 * SHD, nullptr, 0);
    glu_k<<<(TT * SHD) / 256, 256>>>();
    mma_gemm_k<1><<<dim3(HH / 128, TT / 128), 256, GEMM_SMEM>>>(
        (const float*)p_act, sdn, out, HH, (const float*)p_x1, 0);
    mma_gemm_k<2><<<dim3(INTER / 128, CAP / 128, EE), 256, GEMM_SMEM>>>(
        (const float*)p_h2, w1, nullptr, INTER, nullptr, (size_t)INTER * HH);
    mma_gemm_k<3><<<dim3(HH / 128, CAP / 128, EE), 256, GEMM_SMEM>>>(
        nullptr, w2, out, HH, nullptr, (size_t)HH * INTER);
}

// round 6
// speedup vs baseline: 1.3396x; 1.3396x over previous
#include <cuda_runtime.h>
#include <cuda_fp16.h>
#include <math.h>
#include <stdint.h>

// ---------------- problem constants ----------------
#define BB 2
#define SS 1024
#define TT 2048
#define HH 1024
#define NHD 8
#define NOPE 128
#define QHD 192
#define VD 128
#define QCOLS 1536
#define KVC 2048          // rope block of Wkv unused -> skip
#define EE 8
#define CAP 2048
#define INTER 1024
#define SHD 1024

// ---------------- device scratch ----------------
// fp16 (attention path)
__device__ __half g_wq16[QCOLS * HH];
__device__ __half g_wkv16[KVC * HH];
__device__ __half g_wo16[HH * HH];
__device__ __half g_hnorm16[TT * HH];
__device__ __half g_q16[TT * QCOLS];
__device__ __half g_kv16[TT * KVC];
__device__ __half g_attn16[TT * HH];
// fp32 (MoE path, tf32 GEMMs)
__device__ float g_x1[TT * HH];
__device__ float g_h2[TT * HH];
__device__ float g_gu[TT * 2 * SHD];
__device__ float g_act[TT * SHD];
__device__ float g_mid[(size_t)EE * CAP * INTER];
__device__ int   g_cnt[EE];
__device__ int   g_tok[EE * CAP];
__device__ float g_coef[EE * CAP];

// ---------------- helpers ----------------
__device__ __forceinline__ uint32_t s2u(const void* p) {
    return (uint32_t)__cvta_generic_to_shared(p);
}
__device__ __forceinline__ unsigned f2tf(float f) {
    unsigned r; asm("cvt.rna.tf32.f32 %0, %1;" : "=r"(r) : "f"(f)); return r;
}
__device__ __forceinline__ void mma_tf32(float* c, const unsigned* a, const unsigned* b) {
    asm volatile("mma.sync.aligned.m16n8k8.row.col.f32.tf32.tf32.f32 "
                 "{%0,%1,%2,%3},{%4,%5,%6,%7},{%8,%9},{%0,%1,%2,%3};"
                 : "+f"(c[0]), "+f"(c[1]), "+f"(c[2]), "+f"(c[3])
                 : "r"(a[0]), "r"(a[1]), "r"(a[2]), "r"(a[3]), "r"(b[0]), "r"(b[1]));
}
__device__ __forceinline__ void mma16(float* c, const unsigned* a, const unsigned* b) {
    asm volatile("mma.sync.aligned.m16n8k16.row.col.f32.f16.f16.f32 "
                 "{%0,%1,%2,%3},{%4,%5,%6,%7},{%8,%9},{%0,%1,%2,%3};"
                 : "+f"(c[0]), "+f"(c[1]), "+f"(c[2]), "+f"(c[3])
                 : "r"(a[0]), "r"(a[1]), "r"(a[2]), "r"(a[3]), "r"(b[0]), "r"(b[1]));
}
__device__ __forceinline__ void ldsm4(unsigned* r, uint32_t a) {
    asm volatile("ldmatrix.sync.aligned.m8n8.x4.shared.b16 {%0,%1,%2,%3},[%4];"
                 : "=r"(r[0]), "=r"(r[1]), "=r"(r[2]), "=r"(r[3]) : "r"(a));
}
__device__ __forceinline__ void ldsm4t(unsigned* r, uint32_t a) {
    asm volatile("ldmatrix.sync.aligned.m8n8.x4.trans.shared.b16 {%0,%1,%2,%3},[%4];"
                 : "=r"(r[0]), "=r"(r[1]), "=r"(r[2]), "=r"(r[3]) : "r"(a));
}
__device__ __forceinline__ void cpa16(uint32_t d, const void* s) {
    asm volatile("cp.async.cg.shared.global [%0], [%1], 16;" :: "r"(d), "l"(s));
}
__device__ __forceinline__ void cpa_commit() { asm volatile("cp.async.commit_group;"); }
template <int N> __device__ __forceinline__ void cpa_wait() {
    asm volatile("cp.async.wait_group %0;" :: "n"(N));
}
__device__ __forceinline__ unsigned h2u(__half2 h) { return *(unsigned*)&h; }

// ---------------- fp32 -> fp16 conversion ----------------
__global__ void conv_k(const float* __restrict__ s, __half* __restrict__ d, int n) {
    int i = (blockIdx.x * blockDim.x + threadIdx.x) * 8;
    if (i >= n) return;
    float4 a = *(const float4*)(s + i);
    float4 b = *(const float4*)(s + i + 4);
    __half2 h[4] = {__floats2half2_rn(a.x, a.y), __floats2half2_rn(a.z, a.w),
                    __floats2half2_rn(b.x, b.y), __floats2half2_rn(b.z, b.w)};
    *(uint4*)(d + i) = *(uint4*)h;
}

// ---------------- RMSNorm ----------------
// OUT16: write fp16 only.  else fp32 only.
template <bool OUT16>
__global__ void rmsnorm_k(const float* __restrict__ x, const float* __restrict__ w,
                          float* __restrict__ y32, __half* __restrict__ y16) {
    int row = blockIdx.x;
    const float* xr = x + (size_t)row * HH;
    float v[4];
    float s = 0.f;
#pragma unroll
    for (int l = 0; l < 4; l++) {
        v[l] = xr[threadIdx.x + l * 256];
        s += v[l] * v[l];
    }
    __shared__ float red[256];
    red[threadIdx.x] = s;
    __syncthreads();
    for (int off = 128; off > 0; off >>= 1) {
        if (threadIdx.x < off) red[threadIdx.x] += red[threadIdx.x + off];
        __syncthreads();
    }
    float scale = rsqrtf(red[0] * (1.0f / HH) + 1e-6f);
#pragma unroll
    for (int l = 0; l < 4; l++) {
        int i = threadIdx.x + l * 256;
        float o = v[l] * scale * w[i];
        if (OUT16) y16[(size_t)row * HH + i] = __float2half_rn(o);
        else       y32[(size_t)row * HH + i] = o;
    }
}

// ================= tf32 GEMM (MoE path — unchanged from round 4) =================
// C[M,N] = A[M,1024] @ W[N,1024]^T. Tile 128x128x16, 256 thr, warp 32x64.
// MODE 0 plain / 1 +residual / 2 expert-up silu->g_mid / 3 expert-down atomic
#define SMS 20
#define GTILE (128 * SMS)

template <int MODE>
__global__ void __launch_bounds__(256, 2) mma_gemm_k(
    const float* __restrict__ A, const float* __restrict__ W,
    float* __restrict__ C, int N, const float* __restrict__ R, size_t estride)
{
    extern __shared__ __align__(16) float dyn[];
    float* sA = dyn;                // [3][GTILE]
    float* sW = dyn + 3 * GTILE;    // [3][GTILE]
    __shared__ int   s_tok[128];
    __shared__ float s_cf[128];

    const int e  = blockIdx.z;
    const int m0 = blockIdx.y * 128;
    const int n0 = blockIdx.x * 128;
    const int tid = threadIdx.x;

    if (MODE == 2 || MODE == 3) {
        int n_e = g_cnt[e];
        if (m0 >= n_e) return;
        if (tid < 128) {
            int i = m0 + tid;
            bool ok = i < n_e;
            s_tok[tid] = ok ? g_tok[e * CAP + i] : -1;
            if (MODE == 3) s_cf[tid] = ok ? g_coef[e * CAP + i] : 0.f;
        }
        __syncthreads();
    }

    const float* Wbase = W + (size_t)e * estride + (size_t)n0 * 1024;
    const float* Arow  = (MODE == 3) ? (g_mid + ((size_t)e * CAP + m0) * 1024)
                                     : (A + (size_t)m0 * 1024);

    auto issue = [&](int stage, int it) {
        int k0 = it * 16;
        uint32_t da = s2u(sA + stage * GTILE);
        uint32_t dw = s2u(sW + stage * GTILE);
#pragma unroll
        for (int j = 0; j < 2; j++) {
            int q = tid + j * 256;
            int r = q >> 2, c4 = q & 3;
            const float* srcA;
            if (MODE == 2) {
                int tk = s_tok[r]; if (tk < 0) tk = 0;
                srcA = A + (size_t)tk * 1024 + k0 + c4 * 4;
            } else {
                srcA = Arow + (size_t)r * 1024 + k0 + c4 * 4;
            }
            uint32_t off = (uint32_t)(r * SMS + c4 * 4) * 4;
            cpa16(da + off, srcA);
            cpa16(dw + off, Wbase + (size_t)r * 1024 + k0 + c4 * 4);
        }
        cpa_commit();
    };

    const int wid = tid >> 5, lane = tid & 31;
    const int wm = wid & 3, wn = wid >> 2;
    const int lr = lane >> 2, lc = lane & 3;

    float acc[2][8][4] = {};

    issue(0, 0);
    issue(1, 1);
    for (int it = 0; it < 64; ++it) {
        int cur = it % 3;
        cpa_wait<1>();
        __syncthreads();
        if (it + 2 < 64) issue((it + 2) % 3, it + 2);
        const float* As = sA + cur * GTILE;
        const float* Ws = sW + cur * GTILE;
#pragma unroll
        for (int ks = 0; ks < 16; ks += 8) {
            unsigned af[2][4];
#pragma unroll
            for (int mt = 0; mt < 2; mt++) {
                int row = wm * 32 + mt * 16 + lr;
                int k = ks + lc;
                af[mt][0] = f2tf(As[row * SMS + k]);
                af[mt][1] = f2tf(As[(row + 8) * SMS + k]);
                af[mt][2] = f2tf(As[row * SMS + k + 4]);
                af[mt][3] = f2tf(As[(row + 8) * SMS + k + 4]);
            }
#pragma unroll
            for (int nt = 0; nt < 8; nt++) {
                unsigned bf[2];
                int n = wn * 64 + nt * 8 + lr;
                int k = ks + lc;
                bf[0] = f2tf(Ws[n * SMS + k]);
                bf[1] = f2tf(Ws[n * SMS + k + 4]);
                mma_tf32(acc[0][nt], af[0], bf);
                mma_tf32(acc[1][nt], af[1], bf);
            }
        }
    }

#pragma unroll
    for (int mt = 0; mt < 2; mt++)
#pragma unroll
    for (int i = 0; i < 2; i++) {
        int rloc = wm * 32 + mt * 16 + lr + i * 8;
#pragma unroll
        for (int nt = 0; nt < 8; nt++) {
            float v0 = acc[mt][nt][2 * i], v1 = acc[mt][nt][2 * i + 1];
            int col = n0 + wn * 64 + nt * 8 + 2 * lc;
            if (MODE == 0) {
                *(float2*)&C[(size_t)(m0 + rloc) * N + col] = make_float2(v0, v1);
            } else if (MODE == 1) {
                float2 rr = *(const float2*)&R[(size_t)(m0 + rloc) * N + col];
                *(float2*)&C[(size_t)(m0 + rloc) * N + col] = make_float2(v0 + rr.x, v1 + rr.y);
            } else if (MODE == 2) {
                if (s_tok[rloc] >= 0) {
                    float o0 = v0 / (1.f + __expf(-v0));
                    float o1 = v1 / (1.f + __expf(-v1));
                    *(float2*)&g_mid[((size_t)e * CAP + m0 + rloc) * 1024 + col] =
                        make_float2(o0, o1);
                }
            } else {
                int tk = s_tok[rloc];
                if (tk >= 0) {
                    float cf = s_cf[rloc];
                    atomicAdd(&C[(size_t)tk * 1024 + col],     cf * v0);
                    atomicAdd(&C[(size_t)tk * 1024 + col + 1], cf * v1);
                }
            }
        }
    }
}

// ================= fp16 GEMM (attention path) =================
// MODE 1: +residual fp32 out / MODE 4: fp16 out
#define HLDA 40
#define HTILE (128 * HLDA)

template <int MODE>
__global__ void __launch_bounds__(256, 2) hgemm_k(
    const __half* __restrict__ A, const __half* __restrict__ W,
    float* __restrict__ C, __half* __restrict__ C16,
    int N, const float* __restrict__ R)
{
    extern __shared__ __align__(16) __half hdyn[];
    __half* sA = hdyn;                 // [3][HTILE]
    __half* sW = hdyn + 3 * HTILE;

    const int m0 = blockIdx.y * 128;
    const int n0 = blockIdx.x * 128;
    const int tid = threadIdx.x;

    const __half* Wbase = W + (size_t)n0 * 1024;
    const __half* Arow  = A + (size_t)m0 * 1024;

    auto issue = [&](int stage, int it) {
        int k0 = it * 32;
        uint32_t da = s2u(sA + stage * HTILE);
        uint32_t dw = s2u(sW + stage * HTILE);
#pragma unroll
        for (int j = 0; j < 2; j++) {
            int q = tid + j * 256;
            int r = q >> 2, c4 = q & 3;
            uint32_t off = (uint32_t)(r * HLDA + c4 * 8) * 2;
            cpa16(da + off, Arow + (size_t)r * 1024 + k0 + c4 * 8);
            cpa16(dw + off, Wbase + (size_t)r * 1024 + k0 + c4 * 8);
        }
        cpa_commit();
    };

    const int wid = tid >> 5, lane = tid & 31;
    const int wm = wid & 3, wn = wid >> 2;
    const int lr = lane >> 2, lc = lane & 3;
    const int arow = lane & 15, ahalf = lane >> 4;
    const int bg = lane >> 3;
    const int brow = ((bg >> 1) << 3) + (lane & 7);
    const int bcol = (bg & 1) << 3;

    float acc[2][8][4] = {};

    issue(0, 0);
    issue(1, 1);
    for (int it = 0; it < 32; ++it) {
        int cur = it % 3;
        cpa_wait<1>();
        __syncthreads();
        if (it + 2 < 32) issue((it + 2) % 3, it + 2);
        const __half* As = sA + cur * HTILE;
        const __half* Ws = sW + cur * HTILE;
        uint32_t aBase = s2u(As) + (uint32_t)((wm * 32 + arow) * HLDA + ahalf * 8) * 2;
        uint32_t bBase = s2u(Ws) + (uint32_t)((wn * 64 + brow) * HLDA + bcol) * 2;
#pragma unroll
        for (int kc = 0; kc < 2; kc++) {
            unsigned av[2][4];
            ldsm4(av[0], aBase + kc * 32);
            ldsm4(av[1], aBase + kc * 32 + 16 * HLDA * 2);
#pragma unroll
            for (int np = 0; np < 4; np++) {
                unsigned bv[4];
                ldsm4(bv, bBase + kc * 32 + np * 16 * HLDA * 2);
                mma16(acc[0][2 * np],     av[0], bv);
                mma16(acc[0][2 * np + 1], av[0], bv + 2);
                mma16(acc[1][2 * np],     av[1], bv);
                mma16(acc[1][2 * np + 1], av[1], bv + 2);
            }
        }
    }

#pragma unroll
    for (int mt = 0; mt < 2; mt++)
#pragma unroll
    for (int i = 0; i < 2; i++) {
        int rloc = wm * 32 + mt * 16 + lr + i * 8;
#pragma unroll
        for (int nt = 0; nt < 8; nt++) {
            float v0 = acc[mt][nt][2 * i], v1 = acc[mt][nt][2 * i + 1];
            int col = n0 + wn * 64 + nt * 8 + 2 * lc;
            if (MODE == 1) {
                float2 rr = *(const float2*)&R[(size_t)(m0 + rloc) * N + col];
                *(float2*)&C[(size_t)(m0 + rloc) * N + col] = make_float2(v0 + rr.x, v1 + rr.y);
            } else {
                *(__half2*)&C16[(size_t)(m0 + rloc) * N + col] = __floats2half2_rn(v0, v1);
            }
        }
    }
}

// ================= fp16 flash attention =================
#define FLD 136
#define FL_SMEM ((64 + 128 + 128) * FLD * 2)   // 87040 B

__global__ void __launch_bounds__(128) flash16_k(const __half* __restrict__ q16,
                                                 const __half* __restrict__ kv16,
                                                 __half* __restrict__ out16) {
    extern __shared__ __align__(16) __half fsm[];
    __half* Qs = fsm;
    __half* Ks = Qs + 64 * FLD;
    __half* Vs = Ks + 2 * 64 * FLD;

    const int b = blockIdx.z, h = blockIdx.y, qt = blockIdx.x;
    const int tid = threadIdx.x, wid = tid >> 5, lane = tid & 31;
    const int lr = lane >> 2, lc = lane & 3;
    const int t0 = b * SS + qt * 64;
    const float scale = rsqrtf((float)QHD);

    {
        uint32_t qb = s2u(Qs);
#pragma unroll
        for (int j = 0; j < 8; j++) {
            int q = tid + j * 128;
            int r = q >> 4, c = q & 15;
            cpa16(qb + (uint32_t)(r * FLD + c * 8) * 2,
                  q16 + (size_t)(t0 + r) * QCOLS + h * QHD + c * 8);
        }
    }
    auto issue_kv = [&](int stage, int kt) {
        int k0g = b * SS + kt * 64;
        uint32_t kb = s2u(Ks + stage * 64 * FLD);
        uint32_t vb = s2u(Vs + stage * 64 * FLD);
#pragma unroll
        for (int j = 0; j < 8; j++) {
            int q = tid + j * 128;
            int r = q >> 4, c = q & 15;
            const __half* kvrow = kv16 + (size_t)(k0g + r) * KVC;
            cpa16(kb + (uint32_t)(r * FLD + c * 8) * 2, kvrow + h * NOPE + c * 8);
            cpa16(vb + (uint32_t)(r * FLD + c * 8) * 2, kvrow + NHD * NOPE + h * VD + c * 8);
        }
        cpa_commit();
    };
    issue_kv(0, 0);

    const int arow = lane & 15, ahalf = lane >> 4;
    const int bg = lane >> 3;
    const int brow = ((bg >> 1) << 3) + (lane & 7);
    const int bcol = (bg & 1) << 3;
    const int vrow = ((bg & 1) << 3) + (lane & 7);
    const int vcol = (bg >> 1) << 3;

    unsigned qf[8][4];
    float m0r = -1e30f, m1r = -1e30f, l0 = 0.f, l1 = 0.f;
    float o[16][4];
#pragma unroll
    for (int nt = 0; nt < 16; nt++)
#pragma unroll
        for (int j = 0; j < 4; j++) o[nt][j] = 0.f;

    for (int kt = 0; kt <= qt; kt++) {
        int cur = kt & 1;
        cpa_wait<0>();
        __syncthreads();
        if (kt < qt) issue_kv(cur ^ 1, kt + 1);
        if (kt == 0) {
            uint32_t qBase = s2u(Qs) + (uint32_t)((wid * 16 + arow) * FLD + ahalf * 8) * 2;
#pragma unroll
            for (int c = 0; c < 8; c++) ldsm4(qf[c], qBase + c * 32);
        }
        const __half* Kb = Ks + cur * 64 * FLD;
        const __half* Vb = Vs + cur * 64 * FLD;

        float sc[8][4] = {};
        uint32_t kBase = s2u(Kb) + (uint32_t)(brow * FLD + bcol) * 2;
#pragma unroll
        for (int c = 0; c < 8; c++) {
#pragma unroll
            for (int np = 0; np < 4; np++) {
                unsigned bv[4];
                ldsm4(bv, kBase + c * 32 + np * 16 * FLD * 2);
                mma16(sc[2 * np],     qf[c], bv);
                mma16(sc[2 * np + 1], qf[c], bv + 2);
            }
        }
#pragma unroll
        for (int nt = 0; nt < 8; nt++)
#pragma unroll
            for (int j = 0; j < 4; j++) sc[nt][j] *= scale;
        if (kt == qt) {
#pragma unroll
            for (int nt = 0; nt < 8; nt++)
#pragma unroll
                for (int j = 0; j < 4; j++) {
                    int colg = nt * 8 + 2 * lc + (j & 1);
                    int rowg = wid * 16 + lr + (j >> 1) * 8;
                    if (colg > rowg) sc[nt][j] = -1e30f;
                }
        }
        float mx0 = -1e30f, mx1 = -1e30f;
#pragma unroll
        for (int nt = 0; nt < 8; nt++) {
            mx0 = fmaxf(mx0, fmaxf(sc[nt][0], sc[nt][1]));
            mx1 = fmaxf(mx1, fmaxf(sc[nt][2], sc[nt][3]));
        }
        mx0 = fmaxf(mx0, __shfl_xor_sync(0xffffffffu, mx0, 1));
        mx0 = fmaxf(mx0, __shfl_xor_sync(0xffffffffu, mx0, 2));
        mx1 = fmaxf(mx1, __shfl_xor_sync(0xffffffffu, mx1, 1));
        mx1 = fmaxf(mx1, __shfl_xor_sync(0xffffffffu, mx1, 2));
        float mn0 = fmaxf(m0r, mx0), mn1 = fmaxf(m1r, mx1);
        float a0 = __expf(m0r - mn0), a1 = __expf(m1r - mn1);
        float s0 = 0.f, s1 = 0.f;
#pragma unroll
        for (int nt = 0; nt < 8; nt++) {
            sc[nt][0] = __expf(sc[nt][0] - mn0);
            sc[nt][1] = __expf(sc[nt][1] - mn0);
            sc[nt][2] = __expf(sc[nt][2] - mn1);
            sc[nt][3] = __expf(sc[nt][3] - mn1);
            s0 += sc[nt][0] + sc[nt][1];
            s1 += sc[nt][2] + sc[nt][3];
        }
        s0 += __shfl_xor_sync(0xffffffffu, s0, 1);
        s0 += __shfl_xor_sync(0xffffffffu, s0, 2);
        s1 += __shfl_xor_sync(0xffffffffu, s1, 1);
        s1 += __shfl_xor_sync(0xffffffffu, s1, 2);
        l0 = l0 * a0 + s0; l1 = l1 * a1 + s1;
        m0r = mn0; m1r = mn1;
#pragma unroll
        for (int nt = 0; nt < 16; nt++) {
            o[nt][0] *= a0; o[nt][1] *= a0;
            o[nt][2] *= a1; o[nt][3] *= a1;
        }
        uint32_t vBase = s2u(Vb) + (uint32_t)(vrow * FLD + vcol) * 2;
#pragma unroll
        for (int c = 0; c < 4; c++) {
            unsigned pa[4];
            pa[0] = h2u(__floats2half2_rn(sc[2 * c][0],     sc[2 * c][1]));
            pa[1] = h2u(__floats2half2_rn(sc[2 * c][2],     sc[2 * c][3]));
            pa[2] = h2u(__floats2half2_rn(sc[2 * c + 1][0], sc[2 * c + 1][1]));
            pa[3] = h2u(__floats2half2_rn(sc[2 * c + 1][2], sc[2 * c + 1][3]));
#pragma unroll
            for (int nv = 0; nv < 8; nv++) {
                unsigned bv[4];
                ldsm4t(bv, vBase + (uint32_t)(c * 16 * FLD + nv * 16) * 2);
                mma16(o[2 * nv],     pa, bv);
                mma16(o[2 * nv + 1], pa, bv + 2);
            }
        }
    }

    float inv0 = 1.f / l0, inv1 = 1.f / l1;
    int r0 = t0 + wid * 16 + lr, r1 = r0 + 8;
#pragma unroll
    for (int nt = 0; nt < 16; nt++) {
        int col = h * VD + nt * 8 + 2 * lc;
        *(__half2*)&out16[(size_t)r0 * HH + col] = __floats2half2_rn(o[nt][0] * inv0, o[nt][1] * inv0);
        *(__half2*)&out16[(size_t)r1 * HH + col] = __floats2half2_rn(o[nt][2] * inv1, o[nt][3] * inv1);
    }
}

// ---------------- router ----------------
__global__ void zero_cnt_k() {
    if (threadIdx.x < EE) g_cnt[threadIdx.x] = 0;
}

__global__ void gate_k(const float* __restrict__ h2, const float* __restrict__ gw) {
    int warp = (blockIdx.x * blockDim.x + threadIdx.x) >> 5;
    int lane = threadIdx.x & 31;
    if (warp >= TT) return;
    const float* hr = h2 + (size_t)warp * HH;
    float hv[32];
#pragma unroll
    for (int i = 0; i < 32; i++) hv[i] = hr[lane + i * 32];
    float logits[EE];
#pragma unroll
    for (int e = 0; e < EE; e++) {
        const float* wr = gw + e * HH;
        float s = 0.f;
#pragma unroll
        for (int i = 0; i < 32; i++) s = fmaf(hv[i], wr[lane + i * 32], s);
#pragma unroll
        for (int off = 16; off >= 1; off >>= 1)
            s += __shfl_xor_sync(0xffffffffu, s, off);
        logits[e] = s;
    }
    if (lane == 0) {
        int i0 = 0; float v0 = logits[0];
#pragma unroll
        for (int e = 1; e < EE; e++)
            if (logits[e] > v0) { v0 = logits[e]; i0 = e; }
        int i1 = -1; float v1 = -1e30f;
#pragma unroll
        for (int e = 0; e < EE; e++)
            if (e != i0 && logits[e] > v1) { v1 = logits[e]; i1 = e; }
        float r = __expf(v1 - v0);
        float z = 1.f + r;
        float w0 = 1.f / z, w1 = r / z;
        int p0 = atomicAdd(&g_cnt[i0], 1);
        g_tok[i0 * CAP + p0] = warp; g_coef[i0 * CAP + p0] = w0;
        int p1 = atomicAdd(&g_cnt[i1], 1);
        g_tok[i1 * CAP + p1] = warp; g_coef[i1 * CAP + p1] = w1;
    }
}

// ---------------- GLU ----------------
__global__ void glu_k() {
    int idx = blockIdx.x * blockDim.x + threadIdx.x;
    if (idx >= TT * SHD) return;
    int t = idx >> 10;
    int i = idx & 1023;
    float g = g_gu[(size_t)t * (2 * SHD) + i];
    float u = g_gu[(size_t)t * (2 * SHD) + SHD + i];
    g_act[idx] = g / (1.f + __expf(-g)) * u;
}

// ---------------- launch ----------------
extern "C" void kernel_launch(void* const* d_in, const int* in_sizes, int n_in,
                              void* d_out, int out_size) {
    const float* x   = (const float*)d_in[0];
    const float* ln1 = (const float*)d_in[2];
    const float* ln2 = (const float*)d_in[3];
    const float* Wq  = (const float*)d_in[4];
    const float* Wkv = (const float*)d_in[5];
    const float* Wo  = (const float*)d_in[6];
    const float* gw  = (const float*)d_in[7];
    const float* w1  = (const float*)d_in[8];
    const float* w2  = (const float*)d_in[9];
    const float* sgu = (const float*)d_in[10];
    const float* sdn = (const float*)d_in[11];
    float* out = (float*)d_out;

    void *p_wq16, *p_wkv16, *p_wo16, *p_hn16, *p_q16, *p_kv16, *p_attn16;
    void *p_x1, *p_h2, *p_gu, *p_act;
    cudaGetSymbolAddress(&p_wq16,   g_wq16);
    cudaGetSymbolAddress(&p_wkv16,  g_wkv16);
    cudaGetSymbolAddress(&p_wo16,   g_wo16);
    cudaGetSymbolAddress(&p_hn16,   g_hnorm16);
    cudaGetSymbolAddress(&p_q16,    g_q16);
    cudaGetSymbolAddress(&p_kv16,   g_kv16);
    cudaGetSymbolAddress(&p_attn16, g_attn16);
    cudaGetSymbolAddress(&p_x1, g_x1);
    cudaGetSymbolAddress(&p_h2, g_h2);
    cudaGetSymbolAddress(&p_gu, g_gu);
    cudaGetSymbolAddress(&p_act, g_act);

    const int TF_SMEM = 3 * GTILE * 4 * 2;   // 61440 B
    const int H_SMEM  = 6 * HTILE * 2;       // 61440 B
    static bool s_attr = false;
    if (!s_attr) {
        s_attr = true;
        cudaFuncSetAttribute(mma_gemm_k<0>, cudaFuncAttributeMaxDynamicSharedMemorySize, TF_SMEM);
        cudaFuncSetAttribute(mma_gemm_k<1>, cudaFuncAttributeMaxDynamicSharedMemorySize, TF_SMEM);
        cudaFuncSetAttribute(mma_gemm_k<2>, cudaFuncAttributeMaxDynamicSharedMemorySize, TF_SMEM);
        cudaFuncSetAttribute(mma_gemm_k<3>, cudaFuncAttributeMaxDynamicSharedMemorySize, TF_SMEM);
        cudaFuncSetAttribute(hgemm_k<1>,    cudaFuncAttributeMaxDynamicSharedMemorySize, H_SMEM);
        cudaFuncSetAttribute(hgemm_k<4>,    cudaFuncAttributeMaxDynamicSharedMemorySize, H_SMEM);
        cudaFuncSetAttribute(flash16_k,     cudaFuncAttributeMaxDynamicSharedMemorySize, FL_SMEM);
    }

    // fp16 weight conversions (attention weights only)
    auto conv = [&](const float* s, void* d, int n) {
        conv_k<<<(n / 8 + 255) / 256, 256>>>(s, (__half*)d, n);
    };
    conv(Wq,  p_wq16,  QCOLS * HH);
    conv(Wkv, p_wkv16, KVC * HH);
    conv(Wo,  p_wo16,  HH * HH);

    // ---- attention block (fp16 tensor cores) ----
    rmsnorm_k<true><<<TT, 256>>>(x, ln1, nullptr, (__half*)p_hn16);
    hgemm_k<4><<<dim3(QCOLS / 128, TT / 128), 256, H_SMEM>>>(
        (const __half*)p_hn16, (const __half*)p_wq16, nullptr, (__half*)p_q16,
        QCOLS, nullptr);
    hgemm_k<4><<<dim3(KVC / 128, TT / 128), 256, H_SMEM>>>(
        (const __half*)p_hn16, (const __half*)p_wkv16, nullptr, (__half*)p_kv16,
        KVC, nullptr);
    flash16_k<<<dim3(SS / 64, NHD, BB), 128, FL_SMEM>>>(
        (const __half*)p_q16, (const __half*)p_kv16, (__half*)p_attn16);
    hgemm_k<1><<<dim3(HH / 128, TT / 128), 256, H_SMEM>>>(
        (const __half*)p_attn16, (const __half*)p_wo16, (float*)p_x1, nullptr,
        HH, x);

    // ---- MoE block (tf32, round-4 verified) ----
    rmsnorm_k<false><<<TT, 256>>>((const float*)p_x1, ln2, (float*)p_h2, nullptr);
    zero_cnt_k<<<1, 32>>>();
    gate_k<<<TT / 8, 256>>>((const float*)p_h2, gw);
    mma_gemm_k<0><<<dim3((2 * SHD) / 128, TT / 128), 256, TF_SMEM>>>(
        (const float*)p_h2, sgu, (float*)p_gu, 2 * SHD, nullptr, 0);
    glu_k<<<(TT * SHD) / 256, 256>>>();
    mma_gemm_k<1><<<dim3(HH / 128, TT / 128), 256, TF_SMEM>>>(
        (const float*)p_act, sdn, out, HH, (const float*)p_x1, 0);
    mma_gemm_k<2><<<dim3(INTER / 128, CAP / 128, EE), 256, TF_SMEM>>>(
        (const float*)p_h2, w1, nullptr, INTER, nullptr, (size_t)INTER * HH);
    mma_gemm_k<3><<<dim3(HH / 128, CAP / 128, EE), 256, TF_SMEM>>>(
        nullptr, w2, out, HH, nullptr, (size_t)HH * INTER);
}

// round 7
// speedup vs baseline: 1.3795x; 1.0297x over previous
#include <cuda_runtime.h>
#include <cuda_fp16.h>
#include <math.h>
#include <stdint.h>

// ---------------- problem constants ----------------
#define BB 2
#define SS 1024
#define TT 2048
#define HH 1024
#define NHD 8
#define NOPE 128
#define QHD 192
#define VD 128
#define QCOLS 1536
#define KVC 2048          // rope block of Wkv unused -> skip
#define EE 8
#define CAP 2048
#define INTER 1024
#define SHD 1024

// ---------------- device scratch ----------------
// fp16 (attention path)
__device__ __half g_wq16[QCOLS * HH];
__device__ __half g_wkv16[KVC * HH];
__device__ __half g_wo16[HH * HH];
__device__ __half g_hnorm16[TT * HH];
__device__ __half g_q16[TT * QCOLS];
__device__ __half g_kv16[TT * KVC];
__device__ __half g_attn16[TT * HH];
// fp32 (MoE path, tf32 GEMMs) — "p" buffers are k8-permuted + tf32-rounded
__device__ float g_x1[TT * HH];
__device__ float g_h2[TT * HH];       // plain (gate input)
__device__ float g_h2p[TT * HH];      // permuted+rounded (GEMM A input)
__device__ float g_gu[TT * 2 * SHD];
__device__ float g_actp[TT * SHD];
__device__ float g_midp[(size_t)EE * CAP * INTER];
__device__ float g_sgup[2 * SHD * HH];
__device__ float g_sdnp[HH * SHD];
__device__ float g_w1p[(size_t)EE * INTER * HH];
__device__ float g_w2p[(size_t)EE * HH * INTER];
__device__ int   g_cnt[EE];
__device__ int   g_tok[EE * CAP];
__device__ float g_coef[EE * CAP];

// ---------------- helpers ----------------
__device__ __forceinline__ uint32_t s2u(const void* p) {
    return (uint32_t)__cvta_generic_to_shared(p);
}
__device__ __forceinline__ unsigned f2tf(float f) {
    unsigned r; asm("cvt.rna.tf32.f32 %0, %1;" : "=r"(r) : "f"(f)); return r;
}
__device__ __forceinline__ float f2tf_f(float f) {
    return __uint_as_float(f2tf(f));
}
// permuted position within an aligned 8-group: pairs (j, j+4) adjacent
__device__ __forceinline__ int kperm(int j) { return 2 * (j & 3) + (j >> 2); }
__device__ __forceinline__ int permcol(int c) { return (c & ~7) + kperm(c & 7); }

__device__ __forceinline__ void mma_tf32(float* c, const unsigned* a, const unsigned* b) {
    asm volatile("mma.sync.aligned.m16n8k8.row.col.f32.tf32.tf32.f32 "
                 "{%0,%1,%2,%3},{%4,%5,%6,%7},{%8,%9},{%0,%1,%2,%3};"
                 : "+f"(c[0]), "+f"(c[1]), "+f"(c[2]), "+f"(c[3])
                 : "r"(a[0]), "r"(a[1]), "r"(a[2]), "r"(a[3]), "r"(b[0]), "r"(b[1]));
}
__device__ __forceinline__ void mma16(float* c, const unsigned* a, const unsigned* b) {
    asm volatile("mma.sync.aligned.m16n8k16.row.col.f32.f16.f16.f32 "
                 "{%0,%1,%2,%3},{%4,%5,%6,%7},{%8,%9},{%0,%1,%2,%3};"
                 : "+f"(c[0]), "+f"(c[1]), "+f"(c[2]), "+f"(c[3])
                 : "r"(a[0]), "r"(a[1]), "r"(a[2]), "r"(a[3]), "r"(b[0]), "r"(b[1]));
}
__device__ __forceinline__ void ldsm4(unsigned* r, uint32_t a) {
    asm volatile("ldmatrix.sync.aligned.m8n8.x4.shared.b16 {%0,%1,%2,%3},[%4];"
                 : "=r"(r[0]), "=r"(r[1]), "=r"(r[2]), "=r"(r[3]) : "r"(a));
}
__device__ __forceinline__ void ldsm4t(unsigned* r, uint32_t a) {
    asm volatile("ldmatrix.sync.aligned.m8n8.x4.trans.shared.b16 {%0,%1,%2,%3},[%4];"
                 : "=r"(r[0]), "=r"(r[1]), "=r"(r[2]), "=r"(r[3]) : "r"(a));
}
__device__ __forceinline__ void cpa16(uint32_t d, const void* s) {
    asm volatile("cp.async.cg.shared.global [%0], [%1], 16;" :: "r"(d), "l"(s));
}
__device__ __forceinline__ void cpa_commit() { asm volatile("cp.async.commit_group;"); }
template <int N> __device__ __forceinline__ void cpa_wait() {
    asm volatile("cp.async.wait_group %0;" :: "n"(N));
}
__device__ __forceinline__ unsigned h2u(__half2 h) { return *(unsigned*)&h; }

// ---------------- fp32 -> fp16 conversion ----------------
__global__ void conv_k(const float* __restrict__ s, __half* __restrict__ d, int n) {
    int i = (blockIdx.x * blockDim.x + threadIdx.x) * 8;
    if (i >= n) return;
    float4 a = *(const float4*)(s + i);
    float4 b = *(const float4*)(s + i + 4);
    __half2 h[4] = {__floats2half2_rn(a.x, a.y), __floats2half2_rn(a.z, a.w),
                    __floats2half2_rn(b.x, b.y), __floats2half2_rn(b.z, b.w)};
    *(uint4*)(d + i) = *(uint4*)h;
}

// ---------------- fp32 -> tf32-rounded, k8-permuted copy ----------------
__global__ void conv_tfp_k(const float* __restrict__ s, float* __restrict__ d, int n) {
    int g = blockIdx.x * blockDim.x + threadIdx.x;
    if (g * 8 >= n) return;
    const float* sp = s + g * 8;
    float4 a = *(const float4*)sp;
    float4 b = *(const float4*)(sp + 4);
    float v[8] = {a.x, a.y, a.z, a.w, b.x, b.y, b.z, b.w};
    float o[8];
#pragma unroll
    for (int j = 0; j < 8; j++) o[kperm(j)] = f2tf_f(v[j]);
    *(float4*)(d + g * 8)     = make_float4(o[0], o[1], o[2], o[3]);
    *(float4*)(d + g * 8 + 4) = make_float4(o[4], o[5], o[6], o[7]);
}

// ---------------- RMSNorm ----------------
// MODE 0: fp16 out only (attention).  MODE 1: fp32 plain + permuted tf32-rounded.
template <int RMODE>
__global__ void rmsnorm_k(const float* __restrict__ x, const float* __restrict__ w,
                          float* __restrict__ y32, float* __restrict__ y32p,
                          __half* __restrict__ y16) {
    int row = blockIdx.x;
    const float* xr = x + (size_t)row * HH;
    float v[4];
    float s = 0.f;
#pragma unroll
    for (int l = 0; l < 4; l++) {
        v[l] = xr[threadIdx.x + l * 256];
        s += v[l] * v[l];
    }
    __shared__ float red[256];
    red[threadIdx.x] = s;
    __syncthreads();
    for (int off = 128; off > 0; off >>= 1) {
        if (threadIdx.x < off) red[threadIdx.x] += red[threadIdx.x + off];
        __syncthreads();
    }
    float scale = rsqrtf(red[0] * (1.0f / HH) + 1e-6f);
#pragma unroll
    for (int l = 0; l < 4; l++) {
        int i = threadIdx.x + l * 256;
        float o = v[l] * scale * w[i];
        if (RMODE == 0) {
            y16[(size_t)row * HH + i] = __float2half_rn(o);
        } else {
            y32[(size_t)row * HH + i] = o;
            y32p[(size_t)row * HH + permcol(i)] = f2tf_f(o);
        }
    }
}

// ================= tf32 GEMM (MoE path) =================
// C[M,N] = A[M,1024] @ W[N,1024]^T.  A and W are k8-PERMUTED + tf32-rounded.
// Tile 128x128x16, 256 thr, warp 32x64.
// MODE 0 plain fp32 / 1 +residual / 2 expert-up silu->g_midp / 3 expert-down atomic
#define ASTR 24
#define GTILE (128 * ASTR)

template <int MODE>
__global__ void __launch_bounds__(256, 2) mma_gemm_k(
    const float* __restrict__ A, const float* __restrict__ W,
    float* __restrict__ C, int N, const float* __restrict__ R, size_t estride)
{
    extern __shared__ __align__(16) float dyn[];
    float* sA = dyn;                // [3][GTILE]
    float* sW = dyn + 3 * GTILE;    // [3][GTILE]
    __shared__ int   s_tok[128];
    __shared__ float s_cf[128];

    const int e  = blockIdx.z;
    const int m0 = blockIdx.y * 128;
    const int n0 = blockIdx.x * 128;
    const int tid = threadIdx.x;

    if (MODE == 2 || MODE == 3) {
        int n_e = g_cnt[e];
        if (m0 >= n_e) return;
        if (tid < 128) {
            int i = m0 + tid;
            bool ok = i < n_e;
            s_tok[tid] = ok ? g_tok[e * CAP + i] : -1;
            if (MODE == 3) s_cf[tid] = ok ? g_coef[e * CAP + i] : 0.f;
        }
        __syncthreads();
    }

    const float* Wbase = W + (size_t)e * estride + (size_t)n0 * 1024;
    const float* Arow  = (MODE == 3) ? (g_midp + ((size_t)e * CAP + m0) * 1024)
                                     : (A + (size_t)m0 * 1024);

    auto issue = [&](int stage, int it) {
        int k0 = it * 16;
        uint32_t da = s2u(sA + stage * GTILE);
        uint32_t dw = s2u(sW + stage * GTILE);
#pragma unroll
        for (int j = 0; j < 2; j++) {
            int q = tid + j * 256;
            int r = q >> 2, c4 = q & 3;
            const float* srcA;
            if (MODE == 2) {
                int tk = s_tok[r]; if (tk < 0) tk = 0;
                srcA = A + (size_t)tk * 1024 + k0 + c4 * 4;
            } else {
                srcA = Arow + (size_t)r * 1024 + k0 + c4 * 4;
            }
            uint32_t off = (uint32_t)(r * ASTR + c4 * 4) * 4;
            cpa16(da + off, srcA);
            cpa16(dw + off, Wbase + (size_t)r * 1024 + k0 + c4 * 4);
        }
        cpa_commit();
    };

    const int wid = tid >> 5, lane = tid & 31;
    const int wm = wid & 3, wn = wid >> 2;
    const int lr = lane >> 2, lc = lane & 3;

    float acc[2][8][4] = {};

    issue(0, 0);
    issue(1, 1);
    for (int it = 0; it < 64; ++it) {
        int cur = it % 3;
        cpa_wait<1>();
        __syncthreads();
        if (it + 2 < 64) issue((it + 2) % 3, it + 2);
        const float* As = sA + cur * GTILE;
        const float* Ws = sW + cur * GTILE;
#pragma unroll
        for (int ks = 0; ks < 16; ks += 8) {
            unsigned af[2][4];
#pragma unroll
            for (int mt = 0; mt < 2; mt++) {
                int row = wm * 32 + mt * 16 + lr;
                float2 p0 = *(const float2*)&As[row * ASTR + ks + 2 * lc];
                float2 p1 = *(const float2*)&As[(row + 8) * ASTR + ks + 2 * lc];
                af[mt][0] = __float_as_uint(p0.x);
                af[mt][1] = __float_as_uint(p1.x);
                af[mt][2] = __float_as_uint(p0.y);
                af[mt][3] = __float_as_uint(p1.y);
            }
#pragma unroll
            for (int nt = 0; nt < 8; nt++) {
                int n = wn * 64 + nt * 8 + lr;
                float2 q = *(const float2*)&Ws[n * ASTR + ks + 2 * lc];
                unsigned bf[2] = {__float_as_uint(q.x), __float_as_uint(q.y)};
                mma_tf32(acc[0][nt], af[0], bf);
                mma_tf32(acc[1][nt], af[1], bf);
            }
        }
    }

#pragma unroll
    for (int mt = 0; mt < 2; mt++)
#pragma unroll
    for (int i = 0; i < 2; i++) {
        int rloc = wm * 32 + mt * 16 + lr + i * 8;
#pragma unroll
        for (int nt = 0; nt < 8; nt++) {
            float v0 = acc[mt][nt][2 * i], v1 = acc[mt][nt][2 * i + 1];
            int col = n0 + wn * 64 + nt * 8 + 2 * lc;
            if (MODE == 0) {
                *(float2*)&C[(size_t)(m0 + rloc) * N + col] = make_float2(v0, v1);
            } else if (MODE == 1) {
                float2 rr = *(const float2*)&R[(size_t)(m0 + rloc) * N + col];
                *(float2*)&C[(size_t)(m0 + rloc) * N + col] = make_float2(v0 + rr.x, v1 + rr.y);
            } else if (MODE == 2) {
                if (s_tok[rloc] >= 0) {
                    float o0 = v0 / (1.f + __expf(-v0));
                    float o1 = v1 / (1.f + __expf(-v1));
                    float* mr = g_midp + ((size_t)e * CAP + m0 + rloc) * 1024;
                    mr[permcol(col)]     = f2tf_f(o0);
                    mr[permcol(col + 1)] = f2tf_f(o1);
                }
            } else {
                int tk = s_tok[rloc];
                if (tk >= 0) {
                    float cf = s_cf[rloc];
                    atomicAdd(&C[(size_t)tk * 1024 + col],     cf * v0);
                    atomicAdd(&C[(size_t)tk * 1024 + col + 1], cf * v1);
                }
            }
        }
    }
}

// ================= fp16 GEMM (attention path) =================
// MODE 1: +residual fp32 out / MODE 4: fp16 out
#define HLDA 40
#define HTILE (128 * HLDA)

template <int MODE>
__global__ void __launch_bounds__(256, 2) hgemm_k(
    const __half* __restrict__ A, const __half* __restrict__ W,
    float* __restrict__ C, __half* __restrict__ C16,
    int N, const float* __restrict__ R)
{
    extern __shared__ __align__(16) __half hdyn[];
    __half* sA = hdyn;                 // [3][HTILE]
    __half* sW = hdyn + 3 * HTILE;

    const int m0 = blockIdx.y * 128;
    const int n0 = blockIdx.x * 128;
    const int tid = threadIdx.x;

    const __half* Wbase = W + (size_t)n0 * 1024;
    const __half* Arow  = A + (size_t)m0 * 1024;

    auto issue = [&](int stage, int it) {
        int k0 = it * 32;
        uint32_t da = s2u(sA + stage * HTILE);
        uint32_t dw = s2u(sW + stage * HTILE);
#pragma unroll
        for (int j = 0; j < 2; j++) {
            int q = tid + j * 256;
            int r = q >> 2, c4 = q & 3;
            uint32_t off = (uint32_t)(r * HLDA + c4 * 8) * 2;
            cpa16(da + off, Arow + (size_t)r * 1024 + k0 + c4 * 8);
            cpa16(dw + off, Wbase + (size_t)r * 1024 + k0 + c4 * 8);
        }
        cpa_commit();
    };

    const int wid = tid >> 5, lane = tid & 31;
    const int wm = wid & 3, wn = wid >> 2;
    const int lr = lane >> 2, lc = lane & 3;
    const int arow = lane & 15, ahalf = lane >> 4;
    const int bg = lane >> 3;
    const int brow = ((bg >> 1) << 3) + (lane & 7);
    const int bcol = (bg & 1) << 3;

    float acc[2][8][4] = {};

    issue(0, 0);
    issue(1, 1);
    for (int it = 0; it < 32; ++it) {
        int cur = it % 3;
        cpa_wait<1>();
        __syncthreads();
        if (it + 2 < 32) issue((it + 2) % 3, it + 2);
        const __half* As = sA + cur * HTILE;
        const __half* Ws = sW + cur * HTILE;
        uint32_t aBase = s2u(As) + (uint32_t)((wm * 32 + arow) * HLDA + ahalf * 8) * 2;
        uint32_t bBase = s2u(Ws) + (uint32_t)((wn * 64 + brow) * HLDA + bcol) * 2;
#pragma unroll
        for (int kc = 0; kc < 2; kc++) {
            unsigned av[2][4];
            ldsm4(av[0], aBase + kc * 32);
            ldsm4(av[1], aBase + kc * 32 + 16 * HLDA * 2);
#pragma unroll
            for (int np = 0; np < 4; np++) {
                unsigned bv[4];
                ldsm4(bv, bBase + kc * 32 + np * 16 * HLDA * 2);
                mma16(acc[0][2 * np],     av[0], bv);
                mma16(acc[0][2 * np + 1], av[0], bv + 2);
                mma16(acc[1][2 * np],     av[1], bv);
                mma16(acc[1][2 * np + 1], av[1], bv + 2);
            }
        }
    }

#pragma unroll
    for (int mt = 0; mt < 2; mt++)
#pragma unroll
    for (int i = 0; i < 2; i++) {
        int rloc = wm * 32 + mt * 16 + lr + i * 8;
#pragma unroll
        for (int nt = 0; nt < 8; nt++) {
            float v0 = acc[mt][nt][2 * i], v1 = acc[mt][nt][2 * i + 1];
            int col = n0 + wn * 64 + nt * 8 + 2 * lc;
            if (MODE == 1) {
                float2 rr = *(const float2*)&R[(size_t)(m0 + rloc) * N + col];
                *(float2*)&C[(size_t)(m0 + rloc) * N + col] = make_float2(v0 + rr.x, v1 + rr.y);
            } else {
                *(__half2*)&C16[(size_t)(m0 + rloc) * N + col] = __floats2half2_rn(v0, v1);
            }
        }
    }
}

// ================= fp16 flash attention =================
#define FLD 136
#define FL_SMEM ((64 + 128 + 128) * FLD * 2)   // 87040 B

__global__ void __launch_bounds__(128) flash16_k(const __half* __restrict__ q16,
                                                 const __half* __restrict__ kv16,
                                                 __half* __restrict__ out16) {
    extern __shared__ __align__(16) __half fsm[];
    __half* Qs = fsm;
    __half* Ks = Qs + 64 * FLD;
    __half* Vs = Ks + 2 * 64 * FLD;

    const int b = blockIdx.z, h = blockIdx.y, qt = blockIdx.x;
    const int tid = threadIdx.x, wid = tid >> 5, lane = tid & 31;
    const int lr = lane >> 2, lc = lane & 3;
    const int t0 = b * SS + qt * 64;
    const float scale = rsqrtf((float)QHD);

    {
        uint32_t qb = s2u(Qs);
#pragma unroll
        for (int j = 0; j < 8; j++) {
            int q = tid + j * 128;
            int r = q >> 4, c = q & 15;
            cpa16(qb + (uint32_t)(r * FLD + c * 8) * 2,
                  q16 + (size_t)(t0 + r) * QCOLS + h * QHD + c * 8);
        }
    }
    auto issue_kv = [&](int stage, int kt) {
        int k0g = b * SS + kt * 64;
        uint32_t kb = s2u(Ks + stage * 64 * FLD);
        uint32_t vb = s2u(Vs + stage * 64 * FLD);
#pragma unroll
        for (int j = 0; j < 8; j++) {
            int q = tid + j * 128;
            int r = q >> 4, c = q & 15;
            const __half* kvrow = kv16 + (size_t)(k0g + r) * KVC;
            cpa16(kb + (uint32_t)(r * FLD + c * 8) * 2, kvrow + h * NOPE + c * 8);
            cpa16(vb + (uint32_t)(r * FLD + c * 8) * 2, kvrow + NHD * NOPE + h * VD + c * 8);
        }
        cpa_commit();
    };
    issue_kv(0, 0);

    const int arow = lane & 15, ahalf = lane >> 4;
    const int bg = lane >> 3;
    const int brow = ((bg >> 1) << 3) + (lane & 7);
    const int bcol = (bg & 1) << 3;
    const int vrow = ((bg & 1) << 3) + (lane & 7);
    const int vcol = (bg >> 1) << 3;

    unsigned qf[8][4];
    float m0r = -1e30f, m1r = -1e30f, l0 = 0.f, l1 = 0.f;
    float o[16][4];
#pragma unroll
    for (int nt = 0; nt < 16; nt++)
#pragma unroll
        for (int j = 0; j < 4; j++) o[nt][j] = 0.f;

    for (int kt = 0; kt <= qt; kt++) {
        int cur = kt & 1;
        cpa_wait<0>();
        __syncthreads();
        if (kt < qt) issue_kv(cur ^ 1, kt + 1);
        if (kt == 0) {
            uint32_t qBase = s2u(Qs) + (uint32_t)((wid * 16 + arow) * FLD + ahalf * 8) * 2;
#pragma unroll
            for (int c = 0; c < 8; c++) ldsm4(qf[c], qBase + c * 32);
        }
        const __half* Kb = Ks + cur * 64 * FLD;
        const __half* Vb = Vs + cur * 64 * FLD;

        float sc[8][4] = {};
        uint32_t kBase = s2u(Kb) + (uint32_t)(brow * FLD + bcol) * 2;
#pragma unroll
        for (int c = 0; c < 8; c++) {
#pragma unroll
            for (int np = 0; np < 4; np++) {
                unsigned bv[4];
                ldsm4(bv, kBase + c * 32 + np * 16 * FLD * 2);
                mma16(sc[2 * np],     qf[c], bv);
                mma16(sc[2 * np + 1], qf[c], bv + 2);
            }
        }
#pragma unroll
        for (int nt = 0; nt < 8; nt++)
#pragma unroll
            for (int j = 0; j < 4; j++) sc[nt][j] *= scale;
        if (kt == qt) {
#pragma unroll
            for (int nt = 0; nt < 8; nt++)
#pragma unroll
                for (int j = 0; j < 4; j++) {
                    int colg = nt * 8 + 2 * lc + (j & 1);
                    int rowg = wid * 16 + lr + (j >> 1) * 8;
                    if (colg > rowg) sc[nt][j] = -1e30f;
                }
        }
        float mx0 = -1e30f, mx1 = -1e30f;
#pragma unroll
        for (int nt = 0; nt < 8; nt++) {
            mx0 = fmaxf(mx0, fmaxf(sc[nt][0], sc[nt][1]));
            mx1 = fmaxf(mx1, fmaxf(sc[nt][2], sc[nt][3]));
        }
        mx0 = fmaxf(mx0, __shfl_xor_sync(0xffffffffu, mx0, 1));
        mx0 = fmaxf(mx0, __shfl_xor_sync(0xffffffffu, mx0, 2));
        mx1 = fmaxf(mx1, __shfl_xor_sync(0xffffffffu, mx1, 1));
        mx1 = fmaxf(mx1, __shfl_xor_sync(0xffffffffu, mx1, 2));
        float mn0 = fmaxf(m0r, mx0), mn1 = fmaxf(m1r, mx1);
        float a0 = __expf(m0r - mn0), a1 = __expf(m1r - mn1);
        float s0 = 0.f, s1 = 0.f;
#pragma unroll
        for (int nt = 0; nt < 8; nt++) {
            sc[nt][0] = __expf(sc[nt][0] - mn0);
            sc[nt][1] = __expf(sc[nt][1] - mn0);
            sc[nt][2] = __expf(sc[nt][2] - mn1);
            sc[nt][3] = __expf(sc[nt][3] - mn1);
            s0 += sc[nt][0] + sc[nt][1];
            s1 += sc[nt][2] + sc[nt][3];
        }
        s0 += __shfl_xor_sync(0xffffffffu, s0, 1);
        s0 += __shfl_xor_sync(0xffffffffu, s0, 2);
        s1 += __shfl_xor_sync(0xffffffffu, s1, 1);
        s1 += __shfl_xor_sync(0xffffffffu, s1, 2);
        l0 = l0 * a0 + s0; l1 = l1 * a1 + s1;
        m0r = mn0; m1r = mn1;
#pragma unroll
        for (int nt = 0; nt < 16; nt++) {
            o[nt][0] *= a0; o[nt][1] *= a0;
            o[nt][2] *= a1; o[nt][3] *= a1;
        }
        uint32_t vBase = s2u(Vb) + (uint32_t)(vrow * FLD + vcol) * 2;
#pragma unroll
        for (int c = 0; c < 4; c++) {
            unsigned pa[4];
            pa[0] = h2u(__floats2half2_rn(sc[2 * c][0],     sc[2 * c][1]));
            pa[1] = h2u(__floats2half2_rn(sc[2 * c][2],     sc[2 * c][3]));
            pa[2] = h2u(__floats2half2_rn(sc[2 * c + 1][0], sc[2 * c + 1][1]));
            pa[3] = h2u(__floats2half2_rn(sc[2 * c + 1][2], sc[2 * c + 1][3]));
#pragma unroll
            for (int nv = 0; nv < 8; nv++) {
                unsigned bv[4];
                ldsm4t(bv, vBase + (uint32_t)(c * 16 * FLD + nv * 16) * 2);
                mma16(o[2 * nv],     pa, bv);
                mma16(o[2 * nv + 1], pa, bv + 2);
            }
        }
    }

    float inv0 = 1.f / l0, inv1 = 1.f / l1;
    int r0 = t0 + wid * 16 + lr, r1 = r0 + 8;
#pragma unroll
    for (int nt = 0; nt < 16; nt++) {
        int col = h * VD + nt * 8 + 2 * lc;
        *(__half2*)&out16[(size_t)r0 * HH + col] = __floats2half2_rn(o[nt][0] * inv0, o[nt][1] * inv0);
        *(__half2*)&out16[(size_t)r1 * HH + col] = __floats2half2_rn(o[nt][2] * inv1, o[nt][3] * inv1);
    }
}

// ---------------- router ----------------
__global__ void zero_cnt_k() {
    if (threadIdx.x < EE) g_cnt[threadIdx.x] = 0;
}

__global__ void gate_k(const float* __restrict__ h2, const float* __restrict__ gw) {
    int warp = (blockIdx.x * blockDim.x + threadIdx.x) >> 5;
    int lane = threadIdx.x & 31;
    if (warp >= TT) return;
    const float* hr = h2 + (size_t)warp * HH;
    float hv[32];
#pragma unroll
    for (int i = 0; i < 32; i++) hv[i] = hr[lane + i * 32];
    float logits[EE];
#pragma unroll
    for (int e = 0; e < EE; e++) {
        const float* wr = gw + e * HH;
        float s = 0.f;
#pragma unroll
        for (int i = 0; i < 32; i++) s = fmaf(hv[i], wr[lane + i * 32], s);
#pragma unroll
        for (int off = 16; off >= 1; off >>= 1)
            s += __shfl_xor_sync(0xffffffffu, s, off);
        logits[e] = s;
    }
    if (lane == 0) {
        int i0 = 0; float v0 = logits[0];
#pragma unroll
        for (int e = 1; e < EE; e++)
            if (logits[e] > v0) { v0 = logits[e]; i0 = e; }
        int i1 = -1; float v1 = -1e30f;
#pragma unroll
        for (int e = 0; e < EE; e++)
            if (e != i0 && logits[e] > v1) { v1 = logits[e]; i1 = e; }
        float r = __expf(v1 - v0);
        float z = 1.f + r;
        float w0 = 1.f / z, w1 = r / z;
        int p0 = atomicAdd(&g_cnt[i0], 1);
        g_tok[i0 * CAP + p0] = warp; g_coef[i0 * CAP + p0] = w0;
        int p1 = atomicAdd(&g_cnt[i1], 1);
        g_tok[i1 * CAP + p1] = warp; g_coef[i1 * CAP + p1] = w1;
    }
}

// ---------------- GLU (writes permuted + tf32-rounded) ----------------
__global__ void glu_k() {
    int idx = blockIdx.x * blockDim.x + threadIdx.x;
    if (idx >= TT * SHD) return;
    int t = idx >> 10;
    int i = idx & 1023;
    float g = g_gu[(size_t)t * (2 * SHD) + i];
    float u = g_gu[(size_t)t * (2 * SHD) + SHD + i];
    g_actp[(size_t)t * SHD + permcol(i)] = f2tf_f(g / (1.f + __expf(-g)) * u);
}

// ---------------- launch ----------------
extern "C" void kernel_launch(void* const* d_in, const int* in_sizes, int n_in,
                              void* d_out, int out_size) {
    const float* x   = (const float*)d_in[0];
    const float* ln1 = (const float*)d_in[2];
    const float* ln2 = (const float*)d_in[3];
    const float* Wq  = (const float*)d_in[4];
    const float* Wkv = (const float*)d_in[5];
    const float* Wo  = (const float*)d_in[6];
    const float* gw  = (const float*)d_in[7];
    const float* w1  = (const float*)d_in[8];
    const float* w2  = (const float*)d_in[9];
    const float* sgu = (const float*)d_in[10];
    const float* sdn = (const float*)d_in[11];
    float* out = (float*)d_out;

    void *p_wq16, *p_wkv16, *p_wo16, *p_hn16, *p_q16, *p_kv16, *p_attn16;
    void *p_x1, *p_h2, *p_h2p, *p_gu, *p_actp;
    void *p_sgup, *p_sdnp, *p_w1p, *p_w2p;
    cudaGetSymbolAddress(&p_wq16,   g_wq16);
    cudaGetSymbolAddress(&p_wkv16,  g_wkv16);
    cudaGetSymbolAddress(&p_wo16,   g_wo16);
    cudaGetSymbolAddress(&p_hn16,   g_hnorm16);
    cudaGetSymbolAddress(&p_q16,    g_q16);
    cudaGetSymbolAddress(&p_kv16,   g_kv16);
    cudaGetSymbolAddress(&p_attn16, g_attn16);
    cudaGetSymbolAddress(&p_x1,   g_x1);
    cudaGetSymbolAddress(&p_h2,   g_h2);
    cudaGetSymbolAddress(&p_h2p,  g_h2p);
    cudaGetSymbolAddress(&p_gu,   g_gu);
    cudaGetSymbolAddress(&p_actp, g_actp);
    cudaGetSymbolAddress(&p_sgup, g_sgup);
    cudaGetSymbolAddress(&p_sdnp, g_sdnp);
    cudaGetSymbolAddress(&p_w1p,  g_w1p);
    cudaGetSymbolAddress(&p_w2p,  g_w2p);

    const int TF_SMEM = 6 * GTILE * 4;       // 73728 B
    const int H_SMEM  = 6 * HTILE * 2;       // 61440 B
    static bool s_attr = false;
    if (!s_attr) {
        s_attr = true;
        cudaFuncSetAttribute(mma_gemm_k<0>, cudaFuncAttributeMaxDynamicSharedMemorySize, TF_SMEM);
        cudaFuncSetAttribute(mma_gemm_k<1>, cudaFuncAttributeMaxDynamicSharedMemorySize, TF_SMEM);
        cudaFuncSetAttribute(mma_gemm_k<2>, cudaFuncAttributeMaxDynamicSharedMemorySize, TF_SMEM);
        cudaFuncSetAttribute(mma_gemm_k<3>, cudaFuncAttributeMaxDynamicSharedMemorySize, TF_SMEM);
        cudaFuncSetAttribute(hgemm_k<1>,    cudaFuncAttributeMaxDynamicSharedMemorySize, H_SMEM);
        cudaFuncSetAttribute(hgemm_k<4>,    cudaFuncAttributeMaxDynamicSharedMemorySize, H_SMEM);
        cudaFuncSetAttribute(flash16_k,     cudaFuncAttributeMaxDynamicSharedMemorySize, FL_SMEM);
    }

    // fp16 attention weights
    auto conv = [&](const float* s, void* d, int n) {
        conv_k<<<(n / 8 + 255) / 256, 256>>>(s, (__half*)d, n);
    };
    conv(Wq,  p_wq16,  QCOLS * HH);
    conv(Wkv, p_wkv16, KVC * HH);
    conv(Wo,  p_wo16,  HH * HH);
    // tf32-rounded, k8-permuted MoE weights
    auto convp = [&](const float* s, void* d, size_t n) {
        conv_tfp_k<<<(unsigned)((n / 8 + 255) / 256), 256>>>(s, (float*)d, (int)n);
    };
    convp(sgu, p_sgup, (size_t)2 * SHD * HH);
    convp(sdn, p_sdnp, (size_t)HH * SHD);
    convp(w1,  p_w1p,  (size_t)EE * INTER * HH);
    convp(w2,  p_w2p,  (size_t)EE * HH * INTER);

    // ---- attention block (fp16 tensor cores) ----
    rmsnorm_k<0><<<TT, 256>>>(x, ln1, nullptr, nullptr, (__half*)p_hn16);
    hgemm_k<4><<<dim3(QCOLS / 128, TT / 128), 256, H_SMEM>>>(
        (const __half*)p_hn16, (const __half*)p_wq16, nullptr, (__half*)p_q16,
        QCOLS, nullptr);
    hgemm_k<4><<<dim3(KVC / 128, TT / 128), 256, H_SMEM>>>(
        (const __half*)p_hn16, (const __half*)p_wkv16, nullptr, (__half*)p_kv16,
        KVC, nullptr);
    flash16_k<<<dim3(SS / 64, NHD, BB), 128, FL_SMEM>>>(
        (const __half*)p_q16, (const __half*)p_kv16, (__half*)p_attn16);
    hgemm_k<1><<<dim3(HH / 128, TT / 128), 256, H_SMEM>>>(
        (const __half*)p_attn16, (const __half*)p_wo16, (float*)p_x1, nullptr,
        HH, x);

    // ---- MoE block (tf32, pre-rounded permuted operands) ----
    rmsnorm_k<1><<<TT, 256>>>((const float*)p_x1, ln2, (float*)p_h2, (float*)p_h2p, nullptr);
    zero_cnt_k<<<1, 32>>>();
    gate_k<<<TT / 8, 256>>>((const float*)p_h2, gw);
    mma_gemm_k<0><<<dim3((2 * SHD) / 128, TT / 128), 256, TF_SMEM>>>(
        (const float*)p_h2p, (const float*)p_sgup, (float*)p_gu, 2 * SHD, nullptr, 0);
    glu_k<<<(TT * SHD) / 256, 256>>>();
    mma_gemm_k<1><<<dim3(HH / 128, TT / 128), 256, TF_SMEM>>>(
        (const float*)p_actp, (const float*)p_sdnp, out, HH, (const float*)p_x1, 0);
    mma_gemm_k<2><<<dim3(INTER / 128, CAP / 128, EE), 256, TF_SMEM>>>(
        (const float*)p_h2p, (const float*)p_w1p, nullptr, INTER, nullptr, (size_t)INTER * HH);
    mma_gemm_k<3><<<dim3(HH / 128, CAP / 128, EE), 256, TF_SMEM>>>(
        nullptr, (const float*)p_w2p, out, HH, nullptr, (size_t)HH * INTER);
}